// round 8
// baseline (speedup 1.0000x reference)
#include <cuda_runtime.h>
#include <cuda_fp16.h>
#include <cstdint>

// ---------------- problem constants ----------------
#define HEADS   8
#define DK      64
#define KSIZE   7
#define PAD     3
#define S_LEN   256
#define D_MODEL 512
#define M_ROWS  32768            // B*HW*S
#define N_QKV   1536
#define K_DIM   512

// ---------------- GEMM tiling ----------------
#define BM 128
#define BN 128
#define BK 64
#define NCHUNK (K_DIM / BK)      // 8
#define RB 144                   // padded row stride bytes (64 halfs + 8 pad)
#define TILE_BYTES (BM * RB)             // 18432
#define BUF_BYTES  (2 * TILE_BYTES)      // A | B = 36864
#define NSTAGE 3
#define SMEM_TOTAL (NSTAGE * BUF_BYTES)  // 110592

// ---------------- scratch (__device__ globals; no allocs allowed) ----------
__device__ __half  g_qkv[(size_t)M_ROWS * N_QKV];      // 96 MiB fp16 qkv
__device__ __half  g_a  [(size_t)M_ROWS * K_DIM];      // fp16 activations
__device__ __half  g_att[(size_t)M_ROWS * D_MODEL];    // fp16 attention out
__device__ __half  g_wq [(size_t)N_QKV * K_DIM];       // fp16 W_qkv^T
__device__ __half  g_wo [(size_t)D_MODEL * K_DIM];     // fp16 W_out^T

// ---------------- helpers ----------------
__device__ __forceinline__ uint32_t smem_u32(const void* p) {
    uint32_t a;
    asm("{ .reg .u64 t; cvta.to.shared.u64 t, %1; cvt.u32.u64 %0, t; }" : "=r"(a) : "l"(p));
    return a;
}
#define CP_ASYNC16(sa, gp) \
    asm volatile("cp.async.cg.shared.global [%0], [%1], 16;" :: "r"(sa), "l"(gp) : "memory")
#define CP_COMMIT() asm volatile("cp.async.commit_group;" ::: "memory")
#define CP_WAIT1()  asm volatile("cp.async.wait_group 1;" ::: "memory")
#define CP_WAIT0()  asm volatile("cp.async.wait_group 0;" ::: "memory")

#define LDMATRIX_X4(r0, r1, r2, r3, addr) \
    asm volatile("ldmatrix.sync.aligned.m8n8.x4.shared.b16 {%0,%1,%2,%3}, [%4];" \
        : "=r"(r0), "=r"(r1), "=r"(r2), "=r"(r3) : "r"(addr))

__device__ __forceinline__ void mma_f16(float* d, const uint32_t* a, const uint32_t* b) {
    asm volatile(
        "mma.sync.aligned.m16n8k16.row.col.f32.f16.f16.f32 "
        "{%0,%1,%2,%3}, {%4,%5,%6,%7}, {%8,%9}, {%0,%1,%2,%3};"
        : "+f"(d[0]), "+f"(d[1]), "+f"(d[2]), "+f"(d[3])
        : "r"(a[0]), "r"(a[1]), "r"(a[2]), "r"(a[3]), "r"(b[0]), "r"(b[1]));
}

// ---------------------------------------------------------------------------
// Conversions
// ---------------------------------------------------------------------------
__global__ __launch_bounds__(256)
void convert_act_kernel(const float* __restrict__ in, __half* __restrict__ out)
{
    size_t i = ((size_t)blockIdx.x * 256 + threadIdx.x) * 4;
    float4 v = *reinterpret_cast<const float4*>(in + i);
    *reinterpret_cast<__half2*>(out + i)     = __floats2half2_rn(v.x, v.y);
    *reinterpret_cast<__half2*>(out + i + 2) = __floats2half2_rn(v.z, v.w);
}

// W [Kd, Nd] row-major fp32 -> Wt [Nd, Kd] fp16 (K-contiguous)
__global__ __launch_bounds__(256)
void convert_w_kernel(const float* __restrict__ W, __half* __restrict__ Wt,
                      int Kd, int Nd)
{
    size_t idx = (size_t)blockIdx.x * 256 + threadIdx.x;
    int n = (int)(idx / Kd);
    int k = (int)(idx % Kd);
    Wt[idx] = __float2half_rn(W[(size_t)k * Nd + n]);
}

// ---------------------------------------------------------------------------
// fp16 GEMM:  C[M, Ntot] = A[M,512] @ B^T   (B stored [Ntot, 512] K-contig)
// CTA 128x128, BK=64, 8 warps (warp tile 64x32), 3-stage cp.async ring,
// ONE __syncthreads per chunk, ldmatrix.x4 fragments, 2 CTAs/SM.
// OutT = __half (GEMM1, halves store traffic) or float (GEMM2 final out).
// ---------------------------------------------------------------------------
template <typename OutT>
__global__ __launch_bounds__(256, 2)
void gemm_mma_kernel(const __half* __restrict__ A,
                     const __half* __restrict__ B,
                     OutT* __restrict__ C, int Ntot)
{
    extern __shared__ char smem[];
    const uint32_t sb = smem_u32(smem);
    const int tid = threadIdx.x;
    const int wid = tid >> 5;
    const int lid = tid & 31;
    const int warp_m = wid & 1;          // 0..1 -> 64 rows
    const int warp_n = wid >> 1;         // 0..3 -> 32 cols
    const int g   = lid >> 2;            // 0..7
    const int cp2 = (lid & 3) * 2;

    const int m0 = blockIdx.y * BM;
    const int n0 = blockIdx.x * BN;

    const uint32_t aByte = (uint32_t)((warp_m * 64 + (lid & 15)) * RB + (lid >> 4) * 16);
    const int bmi = lid >> 3;
    const uint32_t bByte = (uint32_t)((warp_n * 32 + (bmi >> 1) * 8 + (lid & 7)) * RB
                                      + (bmi & 1) * 16);

    const __half* baseptr[2] = { A + (size_t)m0 * K_DIM, B + (size_t)n0 * K_DIM };

    auto load_chunk = [&](int c, int s) {
        const int kof = c * BK;
        const uint32_t sbase = sb + s * BUF_BYTES;
        #pragma unroll
        for (int i = 0; i < 8; i++) {
            const int u    = tid + i * 256;          // 0..2047
            const int t    = u >> 10;                // tile 0..1
            const int v    = u & 1023;
            const int row  = v >> 3;
            const int quad = v & 7;
            const uint32_t sa = sbase + t * TILE_BYTES + row * RB + quad * 16;
            const __half* gp = baseptr[t] + (size_t)row * K_DIM + kof + quad * 8;
            CP_ASYNC16(sa, gp);
        }
    };

    float acc[4][4][4];
    #pragma unroll
    for (int i = 0; i < 4; i++)
        #pragma unroll
        for (int j = 0; j < 4; j++)
            #pragma unroll
            for (int q = 0; q < 4; q++) acc[i][j][q] = 0.0f;

    load_chunk(0, 0); CP_COMMIT();
    load_chunk(1, 1); CP_COMMIT();

    for (int c = 0; c < NCHUNK; c++) {
        if (c < NCHUNK - 1) CP_WAIT1(); else CP_WAIT0();
        __syncthreads();

        const uint32_t sbase = sb + (c % NSTAGE) * BUF_BYTES;
        const uint32_t sA = sbase;
        const uint32_t sB = sbase + TILE_BYTES;

        #pragma unroll
        for (int ks = 0; ks < 4; ks++) {
            const uint32_t kByte = (uint32_t)(ks * 32);

            uint32_t rA[4][4], rB[4][2];
            #pragma unroll
            for (int mt = 0; mt < 4; mt++)
                LDMATRIX_X4(rA[mt][0], rA[mt][1], rA[mt][2], rA[mt][3],
                            sA + aByte + kByte + (uint32_t)(mt * 16 * RB));
            LDMATRIX_X4(rB[0][0], rB[0][1], rB[1][0], rB[1][1], sB + bByte + kByte);
            LDMATRIX_X4(rB[2][0], rB[2][1], rB[3][0], rB[3][1],
                        sB + bByte + kByte + (uint32_t)(16 * RB));

            #pragma unroll
            for (int mt = 0; mt < 4; mt++)
                #pragma unroll
                for (int nt = 0; nt < 4; nt++)
                    mma_f16(acc[mt][nt], rA[mt], rB[nt]);
        }

        // Stage (c+2)%3 == (c-1)%3 was fully consumed last iteration by every
        // warp that passed this iteration's barrier. Race-free with one BAR.
        if (c + 2 < NCHUNK) {
            load_chunk(c + 2, (c + 2) % NSTAGE);
            CP_COMMIT();
        }
    }

    // ---- epilogue ----
    #pragma unroll
    for (int mt = 0; mt < 4; mt++) {
        const int row = m0 + warp_m * 64 + mt * 16 + g;
        #pragma unroll
        for (int nt = 0; nt < 4; nt++) {
            const int col = n0 + warp_n * 32 + nt * 8 + cp2;
            if constexpr (sizeof(OutT) == 2) {
                *reinterpret_cast<__half2*>((__half*)C + (size_t)row * Ntot + col) =
                    __floats2half2_rn(acc[mt][nt][0], acc[mt][nt][1]);
                *reinterpret_cast<__half2*>((__half*)C + (size_t)(row + 8) * Ntot + col) =
                    __floats2half2_rn(acc[mt][nt][2], acc[mt][nt][3]);
            } else {
                *reinterpret_cast<float2*>((float*)C + (size_t)row * Ntot + col) =
                    make_float2(acc[mt][nt][0], acc[mt][nt][1]);
                *reinterpret_cast<float2*>((float*)C + (size_t)(row + 8) * Ntot + col) =
                    make_float2(acc[mt][nt][2], acc[mt][nt][3]);
            }
        }
    }
}

// ---------------------------------------------------------------------------
// Local attention: one block per row, one warp per head. fp16 qkv in,
// fp32 math, fp16 out. Lane owns dims {2*lane, 2*lane+1} -> half2 loads.
// ---------------------------------------------------------------------------
__global__ __launch_bounds__(256)
void local_attn_kernel(const __half* __restrict__ qkv,
                       const float* __restrict__ pos_bias,
                       __half* __restrict__ out)
{
    const int m    = blockIdx.x;
    const int seq  = m & (S_LEN - 1);
    const int base = m - seq;
    const int h    = threadIdx.x >> 5;
    const int lane = threadIdx.x & 31;
    const int d2   = lane * 2;

    const float2 qv = __half22float2(
        *reinterpret_cast<const __half2*>(qkv + (size_t)m * N_QKV + h * DK + d2));
    const float q0 = qv.x * 0.125f;
    const float q1 = qv.y * 0.125f;

    const float* bias_row = pos_bias + ((size_t)h * S_LEN + seq) * KSIZE;

    float logit[KSIZE];
    #pragma unroll
    for (int j = 0; j < KSIZE; j++) {
        const int s2 = seq + j - PAD;
        float p = 0.0f;
        if (s2 >= 0 && s2 < S_LEN) {
            const float2 kv = __half22float2(*reinterpret_cast<const __half2*>(
                qkv + (size_t)(base + s2) * N_QKV + D_MODEL + h * DK + d2));
            p = q0 * kv.x + q1 * kv.y;
        }
        #pragma unroll
        for (int off = 16; off > 0; off >>= 1)
            p += __shfl_xor_sync(0xffffffffu, p, off);
        logit[j] = p + bias_row[j];
    }

    float mx = logit[0];
    #pragma unroll
    for (int j = 1; j < KSIZE; j++) mx = fmaxf(mx, logit[j]);
    float e[KSIZE], sum = 0.0f;
    #pragma unroll
    for (int j = 0; j < KSIZE; j++) { e[j] = __expf(logit[j] - mx); sum += e[j]; }
    const float inv = 1.0f / sum;

    float o0 = 0.0f, o1 = 0.0f;
    #pragma unroll
    for (int j = 0; j < KSIZE; j++) {
        const int s2 = seq + j - PAD;
        if (s2 >= 0 && s2 < S_LEN) {
            const float2 vv = __half22float2(*reinterpret_cast<const __half2*>(
                qkv + (size_t)(base + s2) * N_QKV + 2 * D_MODEL + h * DK + d2));
            const float a = e[j] * inv;
            o0 += a * vv.x;
            o1 += a * vv.y;
        }
    }

    *reinterpret_cast<__half2*>(out + (size_t)m * D_MODEL + h * DK + d2) =
        __floats2half2_rn(o0, o1);
}

// ---------------------------------------------------------------------------
// Launch
// ---------------------------------------------------------------------------
extern "C" void kernel_launch(void* const* d_in, const int* in_sizes, int n_in,
                              void* d_out, int out_size)
{
    const float* inputs   = (const float*)d_in[0];
    const float* pos_bias = (const float*)d_in[1];
    const float* W_qkv    = (const float*)d_in[2];
    const float* W_out    = (const float*)d_in[3];
    float*       out      = (float*)d_out;

    __half *qkv, *a16, *att, *wq, *wo;
    cudaGetSymbolAddress((void**)&qkv, g_qkv);
    cudaGetSymbolAddress((void**)&a16, g_a);
    cudaGetSymbolAddress((void**)&att, g_att);
    cudaGetSymbolAddress((void**)&wq,  g_wq);
    cudaGetSymbolAddress((void**)&wo,  g_wo);

    cudaFuncSetAttribute(gemm_mma_kernel<__half>,
                         cudaFuncAttributeMaxDynamicSharedMemorySize, SMEM_TOTAL);
    cudaFuncSetAttribute(gemm_mma_kernel<float>,
                         cudaFuncAttributeMaxDynamicSharedMemorySize, SMEM_TOTAL);

    // 0) Conversions
    convert_act_kernel<<<(M_ROWS * K_DIM / 4) / 256, 256>>>(inputs, a16);
    convert_w_kernel<<<(N_QKV * K_DIM) / 256, 256>>>(W_qkv, wq, K_DIM, N_QKV);
    convert_w_kernel<<<(D_MODEL * K_DIM) / 256, 256>>>(W_out, wo, K_DIM, D_MODEL);

    // 1) QKV projection: [32768,512] @ [512,1536] -> fp16
    {
        dim3 grid(N_QKV / BN, M_ROWS / BM);
        gemm_mma_kernel<__half><<<grid, 256, SMEM_TOTAL>>>(a16, wq, qkv, N_QKV);
    }
    // 2) Local windowed attention
    local_attn_kernel<<<M_ROWS, 256>>>(qkv, pos_bias, att);
    // 3) Output projection: [32768,512] @ [512,512] -> fp32
    {
        dim3 grid(D_MODEL / BN, M_ROWS / BM);
        gemm_mma_kernel<float><<<grid, 256, SMEM_TOTAL>>>(att, wo, out, D_MODEL);
    }
}